// round 16
// baseline (speedup 1.0000x reference)
#include <cuda_runtime.h>
#include <cuda_fp16.h>
#include <cstdint>
#include <math.h>

// ---------------------------------------------------------------------------
// GPT-2 block: B=8, S=1024, D=1024, H=16, Hd=64
// ---------------------------------------------------------------------------
#define B_ 8
#define S_ 1024
#define D_ 1024
#define H_ 16
#define HD_ 64
#define M_ (B_ * S_)          // 8192 rows

// Scratch (device globals; no allocation allowed in kernel_launch)
__device__ __half g_h  [M_ * D_];
__device__ __half g_qkv[M_ * 3 * D_];
__device__ __half g_ctx[M_ * D_];
__device__ float  g_h1 [M_ * D_];
__device__ __half g_h2 [M_ * D_];
__device__ __half g_ff [M_ * 4 * D_];
// transposed weights [N, K] fp16
__device__ __half g_wqkv[3 * D_ * D_];
__device__ __half g_wpr [D_ * D_];
__device__ __half g_wfc [4 * D_ * D_];
__device__ __half g_wp2 [4 * D_ * D_];

// ---------------------------------------------------------------------------
// helpers
// ---------------------------------------------------------------------------
__device__ __forceinline__ uint32_t smem_u32(const void* p) {
    uint32_t a;
    asm("{ .reg .u64 t; cvta.to.shared.u64 t, %1; cvt.u32.u64 %0, t; }"
        : "=r"(a) : "l"(p));
    return a;
}
__device__ __forceinline__ void cp16(uint32_t dst, const void* src) {
    asm volatile("cp.async.cg.shared.global [%0], [%1], 16;"
                 :: "r"(dst), "l"(src) : "memory");
}
__device__ __forceinline__ void cp_commit() {
    asm volatile("cp.async.commit_group;" ::: "memory");
}
template <int N>
__device__ __forceinline__ void cp_wait() {
    asm volatile("cp.async.wait_group %0;" :: "n"(N) : "memory");
}
__device__ __forceinline__ void mma_f16(float* d, const uint32_t* a, const uint32_t* b) {
    asm volatile(
        "mma.sync.aligned.m16n8k16.row.col.f32.f16.f16.f32 "
        "{%0,%1,%2,%3}, {%4,%5,%6,%7}, {%8,%9}, {%0,%1,%2,%3};"
        : "+f"(d[0]), "+f"(d[1]), "+f"(d[2]), "+f"(d[3])
        : "r"(a[0]), "r"(a[1]), "r"(a[2]), "r"(a[3]), "r"(b[0]), "r"(b[1]));
}
__device__ __forceinline__ void ldm_x4(uint32_t* r, uint32_t addr) {
    asm volatile("ldmatrix.sync.aligned.m8n8.x4.shared.b16 {%0,%1,%2,%3}, [%4];"
                 : "=r"(r[0]), "=r"(r[1]), "=r"(r[2]), "=r"(r[3]) : "r"(addr));
}
__device__ __forceinline__ void ldm_x4_t(uint32_t* r, uint32_t addr) {
    asm volatile("ldmatrix.sync.aligned.m8n8.x4.trans.shared.b16 {%0,%1,%2,%3}, [%4];"
                 : "=r"(r[0]), "=r"(r[1]), "=r"(r[2]), "=r"(r[3]) : "r"(addr));
}
__device__ __forceinline__ float gelu_new(float x) {
    float x3 = x * x * x;
    return 0.5f * x * (1.0f + tanhf(0.7978845608028654f * (x + 0.044715f * x3)));
}
__device__ __forceinline__ uint32_t pack2h(__half a, __half b) {
    __half2 t{a, b};
    return *reinterpret_cast<uint32_t*>(&t);
}

// ---------------------------------------------------------------------------
// LayerNorm body (256 threads, one row)
// ---------------------------------------------------------------------------
__device__ __forceinline__ void ln_row(const float* __restrict__ x,
                                       const float* __restrict__ g,
                                       const float* __restrict__ b,
                                       __half* __restrict__ oh,
                                       int row, float* red) {
    int tid = threadIdx.x;
    const float4* xr = reinterpret_cast<const float4*>(x + (size_t)row * D_);
    float4 v = xr[tid];

    float s = v.x + v.y + v.z + v.w;
    #pragma unroll
    for (int o = 16; o; o >>= 1) s += __shfl_xor_sync(0xffffffffu, s, o);
    if ((tid & 31) == 0) red[tid >> 5] = s;
    __syncthreads();
    float tot = 0.f;
    #pragma unroll
    for (int i = 0; i < 8; i++) tot += red[i];
    float mu = tot * (1.0f / D_);
    __syncthreads();

    float dx = v.x - mu, dy = v.y - mu, dz = v.z - mu, dw = v.w - mu;
    float q = dx * dx + dy * dy + dz * dz + dw * dw;
    #pragma unroll
    for (int o = 16; o; o >>= 1) q += __shfl_xor_sync(0xffffffffu, q, o);
    if ((tid & 31) == 0) red[tid >> 5] = q;
    __syncthreads();
    float qtot = 0.f;
    #pragma unroll
    for (int i = 0; i < 8; i++) qtot += red[i];
    float rstd = rsqrtf(qtot * (1.0f / D_) + 1e-5f);

    const float4 g4 = reinterpret_cast<const float4*>(g)[tid];
    const float4 b4 = reinterpret_cast<const float4*>(b)[tid];
    float o0 = dx * rstd * g4.x + b4.x;
    float o1 = dy * rstd * g4.y + b4.y;
    float o2 = dz * rstd * g4.z + b4.z;
    float o3 = dw * rstd * g4.w + b4.w;

    size_t base = (size_t)row * D_ + tid * 4;
    uint32_t* ohp = reinterpret_cast<uint32_t*>(oh + base);
    ohp[0] = pack2h(__float2half_rn(o0), __float2half_rn(o1));
    ohp[1] = pack2h(__float2half_rn(o2), __float2half_rn(o3));
}

// ---------------------------------------------------------------------------
// Weight-transpose tile: 64 k-cols x 32 n-rows, 128B-coalesced fp16 writes.
// ---------------------------------------------------------------------------
__device__ __forceinline__ void wconv_tile64(const float* __restrict__ W,
                                             __half* __restrict__ T_,
                                             int K, int N, int nx, int ky,
                                             float (*t)[65]) {
    int tx = threadIdx.x & 31, ty = threadIdx.x >> 5;
    int n0 = nx * 32, k0 = ky * 64;
    #pragma unroll
    for (int j = 0; j < 8; j++) {
        int k = ty + j * 8;
        t[tx][k] = W[(size_t)(k0 + k) * N + n0 + tx];
    }
    __syncthreads();
    #pragma unroll
    for (int j = 0; j < 4; j++) {
        int nl = ty + j * 8;
        uint32_t v = pack2h(__float2half_rn(t[nl][2 * tx]),
                            __float2half_rn(t[nl][2 * tx + 1]));
        *reinterpret_cast<uint32_t*>(T_ + (size_t)(n0 + nl) * K + k0 + 2 * tx) = v;
    }
}

// ---------------------------------------------------------------------------
// Fused prep: LN1 (blocks [0, 8192)) + 4 weight transposes (rest).
// ---------------------------------------------------------------------------
__global__ __launch_bounds__(256)
void prep_kernel(const float* __restrict__ x,
                 const float* __restrict__ ln1_g, const float* __restrict__ ln1_b,
                 __half* __restrict__ h,
                 const float* __restrict__ Wqkv, __half* __restrict__ Tqkv,
                 const float* __restrict__ Wpr,  __half* __restrict__ Tpr,
                 const float* __restrict__ Wfc,  __half* __restrict__ Tfc,
                 const float* __restrict__ Wp2,  __half* __restrict__ Tp2) {
    __shared__ float tbuf[32][65];
    int bid = blockIdx.x;
    if (bid < M_) {
        ln_row(x, ln1_g, ln1_b, h, bid, &tbuf[0][0]);
        return;
    }
    int wb = bid - M_;
    if (wb < 1536) {
        wconv_tile64(Wqkv, Tqkv, D_, 3 * D_, wb % 96, wb / 96, tbuf);
    } else if ((wb -= 1536) < 512) {
        wconv_tile64(Wpr, Tpr, D_, D_, wb % 32, wb / 32, tbuf);
    } else if ((wb -= 512) < 2048) {
        wconv_tile64(Wfc, Tfc, D_, 4 * D_, wb % 128, wb / 128, tbuf);
    } else {
        wb -= 2048;
        wconv_tile64(Wp2, Tp2, 4 * D_, D_, wb % 32, wb / 32, tbuf);
    }
}

__global__ void ln_kernel(const float* __restrict__ x,
                          const float* __restrict__ g,
                          const float* __restrict__ b,
                          __half* __restrict__ oh) {
    __shared__ float red[8];
    ln_row(x, g, b, oh, blockIdx.x, red);
}

// ---------------------------------------------------------------------------
// fp16 tensor GEMM via mma.sync.m16n8k16 + ldmatrix.
// CTA tile 256x128, 256 threads = 8 warps (4x2), warp tile 64x64,
// BK=64, 3-stage cp.async(.cg) pipeline, 1 CTA/SM.
// Per ks-step: 8 ldmatrix feed 32 MMAs (0.25 ldm/MMA) and each warp's
// 32 MMAs are a dependency-free chain -> ILP-hidden LDSM latency.
// EPI: 0 = +bias -> fp16 ; 1 = gelu(+bias) -> fp16 ; 2 = +bias+res -> fp32
// ---------------------------------------------------------------------------
#define BK_ 64
#define T_LD 72                        // smem row stride in halfwords (144 B)
#define A_TILE_B (256 * T_LD * 2)      // 36864
#define B_TILE_B (128 * T_LD * 2)      // 18432
#define STAGE_BYTES (A_TILE_B + B_TILE_B)  // 55296
#define SMEM_GEMM (3 * STAGE_BYTES)        // 165888

template <int EPI>
__global__ __launch_bounds__(256, 1)
void tc_gemm(const __half* __restrict__ Ah, const __half* __restrict__ Bh,
             const float* __restrict__ bias, const float* __restrict__ res,
             float* __restrict__ C, __half* __restrict__ Cho,
             int N, int K) {
    extern __shared__ char dsm[];
    const uint32_t sbase = smem_u32(dsm);
    const int tid  = threadIdx.x;
    const int lane = tid & 31;
    const int wid  = tid >> 5;           // 0..7
    const int g    = lane >> 2;
    const int tig  = lane & 3;
    const int mrow = (wid >> 1) * 64;    // 0..192  (4 warps in M)
    const int ncol = (wid & 1) * 64;     // 0..64   (2 warps in N)
    const int cCol = blockIdx.x, cRow = blockIdx.y;
    const int NC = K / BK_;
    const int lr  = lane & 7;
    const int l8  = (lane & 8) ? 8 : 0;
    const int l16 = (lane & 16) ? 8 : 0;

    const __half* Asrc = Ah + (size_t)cRow * 256 * K;
    const __half* Bsrc = Bh + (size_t)cCol * 128 * K;

    auto load_stage = [&](int chunk, int s) {
        const int kk = chunk * BK_;
        const uint32_t st = sbase + s * STAGE_BYTES;
        // A: 256 rows x 8 chunks of 16B = 2048 chunks; 8 per thread
        #pragma unroll
        for (int i = 0; i < 8; i++) {
            int idx = tid + i * 256;
            int r = idx >> 3, ci = idx & 7;
            cp16(st + r * 144 + ci * 16, Asrc + (size_t)r * K + kk + ci * 8);
        }
        // B: 128 rows x 8 = 1024 chunks; 4 per thread
        #pragma unroll
        for (int i = 0; i < 4; i++) {
            int idx = tid + i * 256;
            int r = idx >> 3, ci = idx & 7;
            cp16(st + A_TILE_B + r * 144 + ci * 16, Bsrc + (size_t)r * K + kk + ci * 8);
        }
    };

    float acc[4][8][4];
    #pragma unroll
    for (int i = 0; i < 4; i++)
        #pragma unroll
        for (int j = 0; j < 8; j++)
            #pragma unroll
            for (int r = 0; r < 4; r++) acc[i][j][r] = 0.f;

    load_stage(0, 0); cp_commit();
    load_stage(1, 1); cp_commit();

    for (int c = 0; c < NC; c++) {
        cp_wait<1>();
        __syncthreads();
        if (c + 2 < NC) load_stage(c + 2, (c + 2) % 3);
        cp_commit();

        const uint32_t ust = sbase + (c % 3) * STAGE_BYTES;
        const uint32_t uAh = ust;
        const uint32_t uBh = ust + A_TILE_B;

        #pragma unroll
        for (int ks = 0; ks < 4; ks++) {
            const int k0 = ks * 16;
            uint32_t ah[4][4], bh[8][2];
            #pragma unroll
            for (int mt = 0; mt < 4; mt++) {
                int row = mrow + mt * 16 + lr + l8;
                ldm_x4(ah[mt], uAh + (uint32_t)(row * T_LD + k0 + l16) * 2);
            }
            #pragma unroll
            for (int ntp = 0; ntp < 4; ntp++) {
                int row = ncol + ntp * 16 + lr + l16;
                uint32_t t4[4];
                ldm_x4(t4, uBh + (uint32_t)(row * T_LD + k0 + l8) * 2);
                bh[2 * ntp][0] = t4[0]; bh[2 * ntp][1] = t4[1];
                bh[2 * ntp + 1][0] = t4[2]; bh[2 * ntp + 1][1] = t4[3];
            }
            #pragma unroll
            for (int mt = 0; mt < 4; mt++)
                #pragma unroll
                for (int nt = 0; nt < 8; nt++)
                    mma_f16(acc[mt][nt], ah[mt], bh[nt]);
        }
    }

    // ---- epilogue ----
    const int row_base = cRow * 256 + mrow;
    const int col_base = cCol * 128 + ncol;
    #pragma unroll
    for (int mt = 0; mt < 4; mt++) {
        #pragma unroll
        for (int nt = 0; nt < 8; nt++) {
            int cc = col_base + nt * 8 + tig * 2;
            float b0 = bias[cc], b1 = bias[cc + 1];
            #pragma unroll
            for (int half = 0; half < 2; half++) {
                int r = row_base + mt * 16 + g + half * 8;
                size_t off = (size_t)r * N + cc;
                float v0 = acc[mt][nt][half * 2 + 0] + b0;
                float v1 = acc[mt][nt][half * 2 + 1] + b1;
                if (EPI == 0 || EPI == 1) {
                    if (EPI == 1) { v0 = gelu_new(v0); v1 = gelu_new(v1); }
                    *reinterpret_cast<uint32_t*>(Cho + off) =
                        pack2h(__float2half_rn(v0), __float2half_rn(v1));
                } else {
                    float2 rr = *reinterpret_cast<const float2*>(res + off);
                    v0 += rr.x; v1 += rr.y;
                    *reinterpret_cast<float2*>(C + off) = make_float2(v0, v1);
                }
            }
        }
    }
}

// ---------------------------------------------------------------------------
// Tensor-core flash attention, pure fp16 operands, fp32 accum/softmax.
// Heavy q-tiles launch first. 2 CTAs/SM.
// ---------------------------------------------------------------------------
#define AT_LD 72
#define AT_ARR (64 * AT_LD)                 // elems per array (4608)
#define AT_STAGE (2 * AT_ARR)               // elems per stage (9216)
#define SMEM_ATTN (2 * AT_STAGE * 2)        // bytes: 36864

__global__ __launch_bounds__(256, 2)
void attn_kernel(const __half* __restrict__ qkvh,
                 __half* __restrict__ ctx) {
    extern __shared__ char dsm[];
    const uint32_t usm = smem_u32(dsm);

    const int qt = (S_ / 128 - 1) - blockIdx.x;   // heavy tiles first
    const int h  = blockIdx.y;
    const int b  = blockIdx.z;
    const int tid = threadIdx.x;
    const int wid = tid >> 5;
    const int lane = tid & 31;
    const int g   = lane >> 2;
    const int tig = lane & 3;
    const int lr  = lane & 7;
    const int l8  = (lane & 8) ? 8 : 0;
    const int l16 = (lane & 16) ? 8 : 0;

    const int q0 = qt * 128;
    const int row0 = wid * 16;
    const int LD3 = 3 * D_;
    const size_t bbase = (size_t)b * S_ * LD3 + h * HD_;

    // ---- load Q fragments (scaled by 1/8, exact on fp16) ----
    uint32_t qh[4][4];
    {
        const __half2 s8 = __floats2half2_rn(0.125f, 0.125f);
        const size_t r0a = bbase + (size_t)(q0 + row0 + g) * LD3;
        const size_t r1a = r0a + (size_t)8 * LD3;
        #pragma unroll
        for (int kc = 0; kc < 4; kc++) {
            int col = kc * 16 + 2 * tig;
            #pragma unroll
            for (int e = 0; e < 4; e++) {
                size_t a = ((e & 1) ? r1a : r0a) + col + ((e & 2) ? 8 : 0);
                __half2 vh = *reinterpret_cast<const __half2*>(qkvh + a);
                vh = __hmul2(vh, s8);
                qh[kc][e] = *reinterpret_cast<uint32_t*>(&vh);
            }
        }
    }

    // smem: [stage][arr][64][AT_LD], arr 0 = K, 1 = V
    auto load_tile = [&](int kt, int s) {
        const int kv0 = kt * 64;
        #pragma unroll
        for (int i = 0; i < 2; i++) {
            int c = tid + i * 256;
            int r = c >> 3, c8 = (c & 7) * 8;
            size_t src = bbase + (size_t)(kv0 + r) * LD3 + c8;
            uint32_t dst = usm + (uint32_t)(s * AT_STAGE + r * AT_LD + c8) * 2;
            cp16(dst,              qkvh + src + D_);       // K
            cp16(dst + AT_ARR * 2, qkvh + src + 2 * D_);   // V
        }
    };

    float o[8][4];
    #pragma unroll
    for (int i = 0; i < 8; i++)
        #pragma unroll
        for (int j = 0; j < 4; j++) o[i][j] = 0.f;
    float m0 = -INFINITY, m1 = -INFINITY, l0 = 0.f, l1 = 0.f;

    const int ktmax = 2 * qt + 1;
    load_tile(0, 0); cp_commit();

    for (int kt = 0; kt <= ktmax; kt++) {
        const int s = kt & 1;
        const int kv0 = kt * 64;
        if (kt < ktmax) { load_tile(kt + 1, s ^ 1); cp_commit(); cp_wait<1>(); }
        else            { cp_wait<0>(); }
        __syncthreads();

        const uint32_t uK = usm + (uint32_t)(s * AT_STAGE) * 2;
        const uint32_t uV = uK + AT_ARR * 2;

        // ---- scores S = Qs @ K^T ----
        float sS[8][4];
        #pragma unroll
        for (int i = 0; i < 8; i++)
            #pragma unroll
            for (int j = 0; j < 4; j++) sS[i][j] = 0.f;

        #pragma unroll
        for (int ntp = 0; ntp < 4; ntp++) {
            int krow = ntp * 16 + lr + l16;
            #pragma unroll
            for (int kc = 0; kc < 4; kc++) {
                uint32_t off = (uint32_t)(krow * AT_LD + kc * 16 + l8) * 2;
                uint32_t th[4];
                ldm_x4(th, uK + off);
                uint32_t bh0[2] = {th[0], th[1]}, bh1[2] = {th[2], th[3]};
                mma_f16(sS[2 * ntp],     qh[kc], bh0);
                mma_f16(sS[2 * ntp + 1], qh[kc], bh1);
            }
        }

        // ---- causal mask ----
        if (kv0 + 63 > q0 + row0) {
            int r0g = q0 + row0 + g;
            #pragma unroll
            for (int nt = 0; nt < 8; nt++) {
                int c0 = kv0 + nt * 8 + 2 * tig;
                if (c0 > r0g)     sS[nt][0] = -1e30f;
                if (c0 + 1 > r0g) sS[nt][1] = -1e30f;
                if (c0 > r0g + 8)     sS[nt][2] = -1e30f;
                if (c0 + 1 > r0g + 8) sS[nt][3] = -1e30f;
            }
        }

        // ---- online softmax (rows g and g+8) ----
        float rm0 = -1e30f, rm1 = -1e30f;
        #pragma unroll
        for (int nt = 0; nt < 8; nt++) {
            rm0 = fmaxf(rm0, fmaxf(sS[nt][0], sS[nt][1]));
            rm1 = fmaxf(rm1, fmaxf(sS[nt][2], sS[nt][3]));
        }
        rm0 = fmaxf(rm0, __shfl_xor_sync(0xffffffffu, rm0, 1));
        rm0 = fmaxf(rm0, __shfl_xor_sync(0xffffffffu, rm0, 2));
        rm1 = fmaxf(rm1, __shfl_xor_sync(0xffffffffu, rm1, 1));
        rm1 = fmaxf(rm1, __shfl_xor_sync(0xffffffffu, rm1, 2));
        float nm0 = fmaxf(m0, rm0), nm1 = fmaxf(m1, rm1);
        float a0 = __expf(m0 - nm0), a1 = __expf(m1 - nm1);
        float rs0 = 0.f, rs1 = 0.f;
        #pragma unroll
        for (int nt = 0; nt < 8; nt++) {
            sS[nt][0] = __expf(sS[nt][0] - nm0);
            sS[nt][1] = __expf(sS[nt][1] - nm0);
            sS[nt][2] = __expf(sS[nt][2] - nm1);
            sS[nt][3] = __expf(sS[nt][3] - nm1);
            rs0 += sS[nt][0] + sS[nt][1];
            rs1 += sS[nt][2] + sS[nt][3];
        }
        rs0 += __shfl_xor_sync(0xffffffffu, rs0, 1);
        rs0 += __shfl_xor_sync(0xffffffffu, rs0, 2);
        rs1 += __shfl_xor_sync(0xffffffffu, rs1, 1);
        rs1 += __shfl_xor_sync(0xffffffffu, rs1, 2);
        l0 = l0 * a0 + rs0; l1 = l1 * a1 + rs1;
        m0 = nm0; m1 = nm1;
        #pragma unroll
        for (int nt = 0; nt < 8; nt++) {
            o[nt][0] *= a0; o[nt][1] *= a0;
            o[nt][2] *= a1; o[nt][3] *= a1;
        }

        // ---- pack P as fp16 A-fragments ----
        uint32_t pah[4][4];
        #pragma unroll
        for (int kc2 = 0; kc2 < 4; kc2++) {
            #pragma unroll
            for (int e = 0; e < 4; e++) {
                int nt = 2 * kc2 + (e >> 1);
                int j0 = (e & 1) ? 2 : 0;
                pah[kc2][e] = pack2h(__float2half_rn(sS[nt][j0]),
                                     __float2half_rn(sS[nt][j0 + 1]));
            }
        }

        // ---- O += P @ V ----
        #pragma unroll
        for (int dn = 0; dn < 4; dn++) {
            #pragma unroll
            for (int kc2 = 0; kc2 < 4; kc2++) {
                int vrow = kc2 * 16 + lr + l8;
                uint32_t off = (uint32_t)(vrow * AT_LD + dn * 16 + l16) * 2;
                uint32_t th[4];
                ldm_x4_t(th, uV + off);
                uint32_t bh0[2] = {th[0], th[1]}, bh1[2] = {th[2], th[3]};
                mma_f16(o[2 * dn],     pah[kc2], bh0);
                mma_f16(o[2 * dn + 1], pah[kc2], bh1);
            }
        }
        __syncthreads();
    }

    // ---- write ctx (fp16) ----
    float inv0 = 1.0f / l0, inv1 = 1.0f / l1;
    size_t r0o = ((size_t)b * S_ + q0 + row0 + g) * D_ + h * HD_;
    size_t r1o = r0o + (size_t)8 * D_;
    #pragma unroll
    for (int nt = 0; nt < 8; nt++) {
        int col = nt * 8 + 2 * tig;
        *reinterpret_cast<uint32_t*>(ctx + r0o + col) =
            pack2h(__float2half_rn(o[nt][0] * inv0), __float2half_rn(o[nt][1] * inv0));
        *reinterpret_cast<uint32_t*>(ctx + r1o + col) =
            pack2h(__float2half_rn(o[nt][2] * inv1), __float2half_rn(o[nt][3] * inv1));
    }
}

// ---------------------------------------------------------------------------
// launch
// ---------------------------------------------------------------------------
extern "C" void kernel_launch(void* const* d_in, const int* in_sizes, int n_in,
                              void* d_out, int out_size) {
    const float* x        = (const float*)d_in[0];
    const float* ln1_g    = (const float*)d_in[1];
    const float* ln1_b    = (const float*)d_in[2];
    const float* c_attn_w = (const float*)d_in[3];
    const float* c_attn_b = (const float*)d_in[4];
    const float* c_proj_w = (const float*)d_in[5];
    const float* c_proj_b = (const float*)d_in[6];
    const float* ln2_g    = (const float*)d_in[7];
    const float* ln2_b    = (const float*)d_in[8];
    const float* fc_w     = (const float*)d_in[9];
    const float* fc_b     = (const float*)d_in[10];
    const float* proj_w   = (const float*)d_in[11];
    const float* proj_b   = (const float*)d_in[12];
    float* out = (float*)d_out;

    cudaFuncSetAttribute(tc_gemm<0>, cudaFuncAttributeMaxDynamicSharedMemorySize, SMEM_GEMM);
    cudaFuncSetAttribute(tc_gemm<1>, cudaFuncAttributeMaxDynamicSharedMemorySize, SMEM_GEMM);
    cudaFuncSetAttribute(tc_gemm<2>, cudaFuncAttributeMaxDynamicSharedMemorySize, SMEM_GEMM);
    cudaFuncSetAttribute(attn_kernel, cudaFuncAttributeMaxDynamicSharedMemorySize, SMEM_ATTN);

    __half *h, *qkv, *ctx, *h2, *ff;
    __half *wqkv, *wpr, *wfc, *wp2;
    float *h1;
    cudaGetSymbolAddress((void**)&h, g_h);
    cudaGetSymbolAddress((void**)&qkv, g_qkv);
    cudaGetSymbolAddress((void**)&ctx, g_ctx);
    cudaGetSymbolAddress((void**)&h1, g_h1);
    cudaGetSymbolAddress((void**)&h2, g_h2);
    cudaGetSymbolAddress((void**)&ff, g_ff);
    cudaGetSymbolAddress((void**)&wqkv, g_wqkv);
    cudaGetSymbolAddress((void**)&wpr, g_wpr);
    cudaGetSymbolAddress((void**)&wfc, g_wfc);
    cudaGetSymbolAddress((void**)&wp2, g_wp2);

    // 0. fused prep: LN1 + all weight transposes
    prep_kernel<<<M_ + 6144, 256>>>(x, ln1_g, ln1_b, h,
                                    c_attn_w, wqkv, c_proj_w, wpr,
                                    fc_w, wfc, proj_w, wp2);
    // 2. qkv = h @ Wqkv + b  -> fp16
    tc_gemm<0><<<dim3(3 * D_ / 128, M_ / 256), 256, SMEM_GEMM>>>(
        h, wqkv, c_attn_b, nullptr, nullptr, qkv, 3 * D_, D_);
    // 3. attention -> ctx fp16
    attn_kernel<<<dim3(S_ / 128, H_, B_), 256, SMEM_ATTN>>>(qkv, ctx);
    // 4. h1 = x + ctx @ Wproj + b  (fp32 out)
    tc_gemm<2><<<dim3(D_ / 128, M_ / 256), 256, SMEM_GEMM>>>(
        ctx, wpr, c_proj_b, x, h1, nullptr, D_, D_);
    // 5. h2 = LN2(h1)  -> fp16
    ln_kernel<<<M_, 256>>>(h1, ln2_g, ln2_b, h2);
    // 6. ff = gelu(h2 @ fc_w + fc_b)  -> fp16
    tc_gemm<1><<<dim3(4 * D_ / 128, M_ / 256), 256, SMEM_GEMM>>>(
        h2, wfc, fc_b, nullptr, nullptr, ff, 4 * D_, D_);
    // 7. out = h1 + ff @ proj_w + proj_b  (fp32 out)
    tc_gemm<2><<<dim3(D_ / 128, M_ / 256), 256, SMEM_GEMM>>>(
        ff, wp2, proj_b, h1, out, nullptr, D_, 4 * D_);
}

// round 17
// speedup vs baseline: 1.0391x; 1.0391x over previous
#include <cuda_runtime.h>
#include <cuda_fp16.h>
#include <cstdint>
#include <math.h>

// ---------------------------------------------------------------------------
// GPT-2 block: B=8, S=1024, D=1024, H=16, Hd=64
// ---------------------------------------------------------------------------
#define B_ 8
#define S_ 1024
#define D_ 1024
#define H_ 16
#define HD_ 64
#define M_ (B_ * S_)          // 8192 rows

// Scratch (device globals; no allocation allowed in kernel_launch)
__device__ __half g_h  [M_ * D_];
__device__ __half g_qkv[M_ * 3 * D_];
__device__ __half g_ctx[M_ * D_];
__device__ float  g_h1 [M_ * D_];
__device__ __half g_h2 [M_ * D_];
__device__ __half g_ff [M_ * 4 * D_];
// transposed weights [N, K] fp16
__device__ __half g_wqkv[3 * D_ * D_];
__device__ __half g_wpr [D_ * D_];
__device__ __half g_wfc [4 * D_ * D_];
__device__ __half g_wp2 [4 * D_ * D_];

// ---------------------------------------------------------------------------
// helpers
// ---------------------------------------------------------------------------
__device__ __forceinline__ uint32_t smem_u32(const void* p) {
    uint32_t a;
    asm("{ .reg .u64 t; cvta.to.shared.u64 t, %1; cvt.u32.u64 %0, t; }"
        : "=r"(a) : "l"(p));
    return a;
}
__device__ __forceinline__ void cp16(uint32_t dst, const void* src) {
    asm volatile("cp.async.cg.shared.global [%0], [%1], 16;"
                 :: "r"(dst), "l"(src) : "memory");
}
__device__ __forceinline__ void cp_commit() {
    asm volatile("cp.async.commit_group;" ::: "memory");
}
template <int N>
__device__ __forceinline__ void cp_wait() {
    asm volatile("cp.async.wait_group %0;" :: "n"(N) : "memory");
}
__device__ __forceinline__ void mma_f16(float* d, const uint32_t* a, const uint32_t* b) {
    asm volatile(
        "mma.sync.aligned.m16n8k16.row.col.f32.f16.f16.f32 "
        "{%0,%1,%2,%3}, {%4,%5,%6,%7}, {%8,%9}, {%0,%1,%2,%3};"
        : "+f"(d[0]), "+f"(d[1]), "+f"(d[2]), "+f"(d[3])
        : "r"(a[0]), "r"(a[1]), "r"(a[2]), "r"(a[3]), "r"(b[0]), "r"(b[1]));
}
__device__ __forceinline__ void ldm_x4(uint32_t* r, uint32_t addr) {
    asm volatile("ldmatrix.sync.aligned.m8n8.x4.shared.b16 {%0,%1,%2,%3}, [%4];"
                 : "=r"(r[0]), "=r"(r[1]), "=r"(r[2]), "=r"(r[3]) : "r"(addr));
}
__device__ __forceinline__ void ldm_x4_t(uint32_t* r, uint32_t addr) {
    asm volatile("ldmatrix.sync.aligned.m8n8.x4.trans.shared.b16 {%0,%1,%2,%3}, [%4];"
                 : "=r"(r[0]), "=r"(r[1]), "=r"(r[2]), "=r"(r[3]) : "r"(addr));
}
__device__ __forceinline__ float gelu_new(float x) {
    float x3 = x * x * x;
    return 0.5f * x * (1.0f + tanhf(0.7978845608028654f * (x + 0.044715f * x3)));
}
__device__ __forceinline__ uint32_t pack2h(__half a, __half b) {
    __half2 t{a, b};
    return *reinterpret_cast<uint32_t*>(&t);
}

// ---------------------------------------------------------------------------
// LayerNorm body (256 threads, one row)
// ---------------------------------------------------------------------------
__device__ __forceinline__ void ln_row(const float* __restrict__ x,
                                       const float* __restrict__ g,
                                       const float* __restrict__ b,
                                       __half* __restrict__ oh,
                                       int row, float* red) {
    int tid = threadIdx.x;
    const float4* xr = reinterpret_cast<const float4*>(x + (size_t)row * D_);
    float4 v = xr[tid];

    float s = v.x + v.y + v.z + v.w;
    #pragma unroll
    for (int o = 16; o; o >>= 1) s += __shfl_xor_sync(0xffffffffu, s, o);
    if ((tid & 31) == 0) red[tid >> 5] = s;
    __syncthreads();
    float tot = 0.f;
    #pragma unroll
    for (int i = 0; i < 8; i++) tot += red[i];
    float mu = tot * (1.0f / D_);
    __syncthreads();

    float dx = v.x - mu, dy = v.y - mu, dz = v.z - mu, dw = v.w - mu;
    float q = dx * dx + dy * dy + dz * dz + dw * dw;
    #pragma unroll
    for (int o = 16; o; o >>= 1) q += __shfl_xor_sync(0xffffffffu, q, o);
    if ((tid & 31) == 0) red[tid >> 5] = q;
    __syncthreads();
    float qtot = 0.f;
    #pragma unroll
    for (int i = 0; i < 8; i++) qtot += red[i];
    float rstd = rsqrtf(qtot * (1.0f / D_) + 1e-5f);

    const float4 g4 = reinterpret_cast<const float4*>(g)[tid];
    const float4 b4 = reinterpret_cast<const float4*>(b)[tid];
    float o0 = dx * rstd * g4.x + b4.x;
    float o1 = dy * rstd * g4.y + b4.y;
    float o2 = dz * rstd * g4.z + b4.z;
    float o3 = dw * rstd * g4.w + b4.w;

    size_t base = (size_t)row * D_ + tid * 4;
    uint32_t* ohp = reinterpret_cast<uint32_t*>(oh + base);
    ohp[0] = pack2h(__float2half_rn(o0), __float2half_rn(o1));
    ohp[1] = pack2h(__float2half_rn(o2), __float2half_rn(o3));
}

// ---------------------------------------------------------------------------
// Weight-transpose tile: 64 k-cols x 32 n-rows, 128B-coalesced fp16 writes.
// ---------------------------------------------------------------------------
__device__ __forceinline__ void wconv_tile64(const float* __restrict__ W,
                                             __half* __restrict__ T_,
                                             int K, int N, int nx, int ky,
                                             float (*t)[65]) {
    int tx = threadIdx.x & 31, ty = threadIdx.x >> 5;
    int n0 = nx * 32, k0 = ky * 64;
    #pragma unroll
    for (int j = 0; j < 8; j++) {
        int k = ty + j * 8;
        t[tx][k] = W[(size_t)(k0 + k) * N + n0 + tx];
    }
    __syncthreads();
    #pragma unroll
    for (int j = 0; j < 4; j++) {
        int nl = ty + j * 8;
        uint32_t v = pack2h(__float2half_rn(t[nl][2 * tx]),
                            __float2half_rn(t[nl][2 * tx + 1]));
        *reinterpret_cast<uint32_t*>(T_ + (size_t)(n0 + nl) * K + k0 + 2 * tx) = v;
    }
}

// ---------------------------------------------------------------------------
// Fused prep: LN1 (blocks [0, 8192)) + 4 weight transposes (rest).
// ---------------------------------------------------------------------------
__global__ __launch_bounds__(256)
void prep_kernel(const float* __restrict__ x,
                 const float* __restrict__ ln1_g, const float* __restrict__ ln1_b,
                 __half* __restrict__ h,
                 const float* __restrict__ Wqkv, __half* __restrict__ Tqkv,
                 const float* __restrict__ Wpr,  __half* __restrict__ Tpr,
                 const float* __restrict__ Wfc,  __half* __restrict__ Tfc,
                 const float* __restrict__ Wp2,  __half* __restrict__ Tp2) {
    __shared__ float tbuf[32][65];
    int bid = blockIdx.x;
    if (bid < M_) {
        ln_row(x, ln1_g, ln1_b, h, bid, &tbuf[0][0]);
        return;
    }
    int wb = bid - M_;
    if (wb < 1536) {
        wconv_tile64(Wqkv, Tqkv, D_, 3 * D_, wb % 96, wb / 96, tbuf);
    } else if ((wb -= 1536) < 512) {
        wconv_tile64(Wpr, Tpr, D_, D_, wb % 32, wb / 32, tbuf);
    } else if ((wb -= 512) < 2048) {
        wconv_tile64(Wfc, Tfc, D_, 4 * D_, wb % 128, wb / 128, tbuf);
    } else {
        wb -= 2048;
        wconv_tile64(Wp2, Tp2, 4 * D_, D_, wb % 32, wb / 32, tbuf);
    }
}

__global__ void ln_kernel(const float* __restrict__ x,
                          const float* __restrict__ g,
                          const float* __restrict__ b,
                          __half* __restrict__ oh) {
    __shared__ float red[8];
    ln_row(x, g, b, oh, blockIdx.x, red);
}

// ---------------------------------------------------------------------------
// fp16 tensor GEMM via mma.sync.m16n8k16 + ldmatrix.
// CTA tile 256x128, 512 threads = 16 warps (4x4), warp tile 64x32 (R13 map),
// BK=128, 2-stage cp.async(.cg) pipeline, ONE barrier per chunk:
//   wait(all) -> sync -> issue next-chunk loads (overlap compute) -> compute.
// 1 CTA/SM (204KB smem).
// EPI: 0 = +bias -> fp16 ; 1 = gelu(+bias) -> fp16 ; 2 = +bias+res -> fp32
// ---------------------------------------------------------------------------
#define BK_ 128
#define T_LD 136                       // smem row stride in halfwords (272 B)
#define A_TILE_B (256 * T_LD * 2)      // 69632
#define B_TILE_B (128 * T_LD * 2)      // 34816
#define STAGE_BYTES (A_TILE_B + B_TILE_B)  // 104448
#define SMEM_GEMM (2 * STAGE_BYTES)        // 208896

template <int EPI>
__global__ __launch_bounds__(512, 1)
void tc_gemm(const __half* __restrict__ Ah, const __half* __restrict__ Bh,
             const float* __restrict__ bias, const float* __restrict__ res,
             float* __restrict__ C, __half* __restrict__ Cho,
             int N, int K) {
    extern __shared__ char dsm[];
    const uint32_t sbase = smem_u32(dsm);
    const int tid  = threadIdx.x;
    const int lane = tid & 31;
    const int wid  = tid >> 5;
    const int g    = lane >> 2;
    const int tig  = lane & 3;
    const int mrow = (wid >> 2) * 64;    // 0..192
    const int ncol = (wid & 3) * 32;     // 0..96
    const int cCol = blockIdx.x, cRow = blockIdx.y;
    const int NC = K / BK_;
    const int lr  = lane & 7;
    const int l8  = (lane & 8) ? 8 : 0;
    const int l16 = (lane & 16) ? 8 : 0;

    const __half* Asrc = Ah + (size_t)cRow * 256 * K;
    const __half* Bsrc = Bh + (size_t)cCol * 128 * K;

    auto load_stage = [&](int chunk, int s) {
        const int kk = chunk * BK_;
        const uint32_t st = sbase + s * STAGE_BYTES;
        // A: 256 rows x 16 chunks of 16B = 4096 chunks; 8 per thread
        #pragma unroll
        for (int i = 0; i < 8; i++) {
            int idx = tid + i * 512;
            int r = idx >> 4, ci = idx & 15;
            cp16(st + r * 272 + ci * 16, Asrc + (size_t)r * K + kk + ci * 8);
        }
        // B: 128 rows x 16 = 2048 chunks; 4 per thread
        #pragma unroll
        for (int i = 0; i < 4; i++) {
            int idx = tid + i * 512;
            int r = idx >> 4, ci = idx & 15;
            cp16(st + A_TILE_B + r * 272 + ci * 16, Bsrc + (size_t)r * K + kk + ci * 8);
        }
    };

    float acc[4][4][4];
    #pragma unroll
    for (int i = 0; i < 4; i++)
        #pragma unroll
        for (int j = 0; j < 4; j++)
            #pragma unroll
            for (int r = 0; r < 4; r++) acc[i][j][r] = 0.f;

    load_stage(0, 0); cp_commit();

    for (int c = 0; c < NC; c++) {
        cp_wait<0>();
        __syncthreads();
        // issue next chunk into the other stage; overlaps with compute below.
        // (stage (c+1)&1 held chunk c-1, fully consumed before the barrier.)
        if (c + 1 < NC) { load_stage(c + 1, (c + 1) & 1); cp_commit(); }

        const uint32_t ust = sbase + (c & 1) * STAGE_BYTES;
        const uint32_t uAh = ust;
        const uint32_t uBh = ust + A_TILE_B;

        #pragma unroll
        for (int ks = 0; ks < 8; ks++) {
            const int k0 = ks * 16;
            uint32_t ah[4][4], bh[4][2];
            #pragma unroll
            for (int mt = 0; mt < 4; mt++) {
                int row = mrow + mt * 16 + lr + l8;
                ldm_x4(ah[mt], uAh + (uint32_t)(row * T_LD + k0 + l16) * 2);
            }
            #pragma unroll
            for (int ntp = 0; ntp < 2; ntp++) {
                int row = ncol + ntp * 16 + lr + l16;
                uint32_t t4[4];
                ldm_x4(t4, uBh + (uint32_t)(row * T_LD + k0 + l8) * 2);
                bh[2 * ntp][0] = t4[0]; bh[2 * ntp][1] = t4[1];
                bh[2 * ntp + 1][0] = t4[2]; bh[2 * ntp + 1][1] = t4[3];
            }
            #pragma unroll
            for (int mt = 0; mt < 4; mt++)
                #pragma unroll
                for (int nt = 0; nt < 4; nt++)
                    mma_f16(acc[mt][nt], ah[mt], bh[nt]);
        }
    }

    // ---- epilogue ----
    const int row_base = cRow * 256 + mrow;
    const int col_base = cCol * 128 + ncol;
    #pragma unroll
    for (int mt = 0; mt < 4; mt++) {
        #pragma unroll
        for (int nt = 0; nt < 4; nt++) {
            int cc = col_base + nt * 8 + tig * 2;
            float b0 = bias[cc], b1 = bias[cc + 1];
            #pragma unroll
            for (int half = 0; half < 2; half++) {
                int r = row_base + mt * 16 + g + half * 8;
                size_t off = (size_t)r * N + cc;
                float v0 = acc[mt][nt][half * 2 + 0] + b0;
                float v1 = acc[mt][nt][half * 2 + 1] + b1;
                if (EPI == 0 || EPI == 1) {
                    if (EPI == 1) { v0 = gelu_new(v0); v1 = gelu_new(v1); }
                    *reinterpret_cast<uint32_t*>(Cho + off) =
                        pack2h(__float2half_rn(v0), __float2half_rn(v1));
                } else {
                    float2 rr = *reinterpret_cast<const float2*>(res + off);
                    v0 += rr.x; v1 += rr.y;
                    *reinterpret_cast<float2*>(C + off) = make_float2(v0, v1);
                }
            }
        }
    }
}

// ---------------------------------------------------------------------------
// Tensor-core flash attention, pure fp16 operands, fp32 accum/softmax.
// Heavy q-tiles launch first. 2 CTAs/SM.
// ---------------------------------------------------------------------------
#define AT_LD 72
#define AT_ARR (64 * AT_LD)                 // elems per array (4608)
#define AT_STAGE (2 * AT_ARR)               // elems per stage (9216)
#define SMEM_ATTN (2 * AT_STAGE * 2)        // bytes: 36864

__global__ __launch_bounds__(256, 2)
void attn_kernel(const __half* __restrict__ qkvh,
                 __half* __restrict__ ctx) {
    extern __shared__ char dsm[];
    const uint32_t usm = smem_u32(dsm);

    const int qt = (S_ / 128 - 1) - blockIdx.x;   // heavy tiles first
    const int h  = blockIdx.y;
    const int b  = blockIdx.z;
    const int tid = threadIdx.x;
    const int wid = tid >> 5;
    const int lane = tid & 31;
    const int g   = lane >> 2;
    const int tig = lane & 3;
    const int lr  = lane & 7;
    const int l8  = (lane & 8) ? 8 : 0;
    const int l16 = (lane & 16) ? 8 : 0;

    const int q0 = qt * 128;
    const int row0 = wid * 16;
    const int LD3 = 3 * D_;
    const size_t bbase = (size_t)b * S_ * LD3 + h * HD_;

    // ---- load Q fragments (scaled by 1/8, exact on fp16) ----
    uint32_t qh[4][4];
    {
        const __half2 s8 = __floats2half2_rn(0.125f, 0.125f);
        const size_t r0a = bbase + (size_t)(q0 + row0 + g) * LD3;
        const size_t r1a = r0a + (size_t)8 * LD3;
        #pragma unroll
        for (int kc = 0; kc < 4; kc++) {
            int col = kc * 16 + 2 * tig;
            #pragma unroll
            for (int e = 0; e < 4; e++) {
                size_t a = ((e & 1) ? r1a : r0a) + col + ((e & 2) ? 8 : 0);
                __half2 vh = *reinterpret_cast<const __half2*>(qkvh + a);
                vh = __hmul2(vh, s8);
                qh[kc][e] = *reinterpret_cast<uint32_t*>(&vh);
            }
        }
    }

    // smem: [stage][arr][64][AT_LD], arr 0 = K, 1 = V
    auto load_tile = [&](int kt, int s) {
        const int kv0 = kt * 64;
        #pragma unroll
        for (int i = 0; i < 2; i++) {
            int c = tid + i * 256;
            int r = c >> 3, c8 = (c & 7) * 8;
            size_t src = bbase + (size_t)(kv0 + r) * LD3 + c8;
            uint32_t dst = usm + (uint32_t)(s * AT_STAGE + r * AT_LD + c8) * 2;
            cp16(dst,              qkvh + src + D_);       // K
            cp16(dst + AT_ARR * 2, qkvh + src + 2 * D_);   // V
        }
    };

    float o[8][4];
    #pragma unroll
    for (int i = 0; i < 8; i++)
        #pragma unroll
        for (int j = 0; j < 4; j++) o[i][j] = 0.f;
    float m0 = -INFINITY, m1 = -INFINITY, l0 = 0.f, l1 = 0.f;

    const int ktmax = 2 * qt + 1;
    load_tile(0, 0); cp_commit();

    for (int kt = 0; kt <= ktmax; kt++) {
        const int s = kt & 1;
        const int kv0 = kt * 64;
        if (kt < ktmax) { load_tile(kt + 1, s ^ 1); cp_commit(); cp_wait<1>(); }
        else            { cp_wait<0>(); }
        __syncthreads();

        const uint32_t uK = usm + (uint32_t)(s * AT_STAGE) * 2;
        const uint32_t uV = uK + AT_ARR * 2;

        // ---- scores S = Qs @ K^T ----
        float sS[8][4];
        #pragma unroll
        for (int i = 0; i < 8; i++)
            #pragma unroll
            for (int j = 0; j < 4; j++) sS[i][j] = 0.f;

        #pragma unroll
        for (int ntp = 0; ntp < 4; ntp++) {
            int krow = ntp * 16 + lr + l16;
            #pragma unroll
            for (int kc = 0; kc < 4; kc++) {
                uint32_t off = (uint32_t)(krow * AT_LD + kc * 16 + l8) * 2;
                uint32_t th[4];
                ldm_x4(th, uK + off);
                uint32_t bh0[2] = {th[0], th[1]}, bh1[2] = {th[2], th[3]};
                mma_f16(sS[2 * ntp],     qh[kc], bh0);
                mma_f16(sS[2 * ntp + 1], qh[kc], bh1);
            }
        }

        // ---- causal mask ----
        if (kv0 + 63 > q0 + row0) {
            int r0g = q0 + row0 + g;
            #pragma unroll
            for (int nt = 0; nt < 8; nt++) {
                int c0 = kv0 + nt * 8 + 2 * tig;
                if (c0 > r0g)     sS[nt][0] = -1e30f;
                if (c0 + 1 > r0g) sS[nt][1] = -1e30f;
                if (c0 > r0g + 8)     sS[nt][2] = -1e30f;
                if (c0 + 1 > r0g + 8) sS[nt][3] = -1e30f;
            }
        }

        // ---- online softmax (rows g and g+8) ----
        float rm0 = -1e30f, rm1 = -1e30f;
        #pragma unroll
        for (int nt = 0; nt < 8; nt++) {
            rm0 = fmaxf(rm0, fmaxf(sS[nt][0], sS[nt][1]));
            rm1 = fmaxf(rm1, fmaxf(sS[nt][2], sS[nt][3]));
        }
        rm0 = fmaxf(rm0, __shfl_xor_sync(0xffffffffu, rm0, 1));
        rm0 = fmaxf(rm0, __shfl_xor_sync(0xffffffffu, rm0, 2));
        rm1 = fmaxf(rm1, __shfl_xor_sync(0xffffffffu, rm1, 1));
        rm1 = fmaxf(rm1, __shfl_xor_sync(0xffffffffu, rm1, 2));
        float nm0 = fmaxf(m0, rm0), nm1 = fmaxf(m1, rm1);
        float a0 = __expf(m0 - nm0), a1 = __expf(m1 - nm1);
        float rs0 = 0.f, rs1 = 0.f;
        #pragma unroll
        for (int nt = 0; nt < 8; nt++) {
            sS[nt][0] = __expf(sS[nt][0] - nm0);
            sS[nt][1] = __expf(sS[nt][1] - nm0);
            sS[nt][2] = __expf(sS[nt][2] - nm1);
            sS[nt][3] = __expf(sS[nt][3] - nm1);
            rs0 += sS[nt][0] + sS[nt][1];
            rs1 += sS[nt][2] + sS[nt][3];
        }
        rs0 += __shfl_xor_sync(0xffffffffu, rs0, 1);
        rs0 += __shfl_xor_sync(0xffffffffu, rs0, 2);
        rs1 += __shfl_xor_sync(0xffffffffu, rs1, 1);
        rs1 += __shfl_xor_sync(0xffffffffu, rs1, 2);
        l0 = l0 * a0 + rs0; l1 = l1 * a1 + rs1;
        m0 = nm0; m1 = nm1;
        #pragma unroll
        for (int nt = 0; nt < 8; nt++) {
            o[nt][0] *= a0; o[nt][1] *= a0;
            o[nt][2] *= a1; o[nt][3] *= a1;
        }

        // ---- pack P as fp16 A-fragments ----
        uint32_t pah[4][4];
        #pragma unroll
        for (int kc2 = 0; kc2 < 4; kc2++) {
            #pragma unroll
            for (int e = 0; e < 4; e++) {
                int nt = 2 * kc2 + (e >> 1);
                int j0 = (e & 1) ? 2 : 0;
                pah[kc2][e] = pack2h(__float2half_rn(sS[nt][j0]),
                                     __float2half_rn(sS[nt][j0 + 1]));
            }
        }

        // ---- O += P @ V ----
        #pragma unroll
        for (int dn = 0; dn < 4; dn++) {
            #pragma unroll
            for (int kc2 = 0; kc2 < 4; kc2++) {
                int vrow = kc2 * 16 + lr + l8;
                uint32_t off = (uint32_t)(vrow * AT_LD + dn * 16 + l16) * 2;
                uint32_t th[4];
                ldm_x4_t(th, uV + off);
                uint32_t bh0[2] = {th[0], th[1]}, bh1[2] = {th[2], th[3]};
                mma_f16(o[2 * dn],     pah[kc2], bh0);
                mma_f16(o[2 * dn + 1], pah[kc2], bh1);
            }
        }
        __syncthreads();
    }

    // ---- write ctx (fp16) ----
    float inv0 = 1.0f / l0, inv1 = 1.0f / l1;
    size_t r0o = ((size_t)b * S_ + q0 + row0 + g) * D_ + h * HD_;
    size_t r1o = r0o + (size_t)8 * D_;
    #pragma unroll
    for (int nt = 0; nt < 8; nt++) {
        int col = nt * 8 + 2 * tig;
        *reinterpret_cast<uint32_t*>(ctx + r0o + col) =
            pack2h(__float2half_rn(o[nt][0] * inv0), __float2half_rn(o[nt][1] * inv0));
        *reinterpret_cast<uint32_t*>(ctx + r1o + col) =
            pack2h(__float2half_rn(o[nt][2] * inv1), __float2half_rn(o[nt][3] * inv1));
    }
}

// ---------------------------------------------------------------------------
// launch
// ---------------------------------------------------------------------------
extern "C" void kernel_launch(void* const* d_in, const int* in_sizes, int n_in,
                              void* d_out, int out_size) {
    const float* x        = (const float*)d_in[0];
    const float* ln1_g    = (const float*)d_in[1];
    const float* ln1_b    = (const float*)d_in[2];
    const float* c_attn_w = (const float*)d_in[3];
    const float* c_attn_b = (const float*)d_in[4];
    const float* c_proj_w = (const float*)d_in[5];
    const float* c_proj_b = (const float*)d_in[6];
    const float* ln2_g    = (const float*)d_in[7];
    const float* ln2_b    = (const float*)d_in[8];
    const float* fc_w     = (const float*)d_in[9];
    const float* fc_b     = (const float*)d_in[10];
    const float* proj_w   = (const float*)d_in[11];
    const float* proj_b   = (const float*)d_in[12];
    float* out = (float*)d_out;

    cudaFuncSetAttribute(tc_gemm<0>, cudaFuncAttributeMaxDynamicSharedMemorySize, SMEM_GEMM);
    cudaFuncSetAttribute(tc_gemm<1>, cudaFuncAttributeMaxDynamicSharedMemorySize, SMEM_GEMM);
    cudaFuncSetAttribute(tc_gemm<2>, cudaFuncAttributeMaxDynamicSharedMemorySize, SMEM_GEMM);
    cudaFuncSetAttribute(attn_kernel, cudaFuncAttributeMaxDynamicSharedMemorySize, SMEM_ATTN);

    __half *h, *qkv, *ctx, *h2, *ff;
    __half *wqkv, *wpr, *wfc, *wp2;
    float *h1;
    cudaGetSymbolAddress((void**)&h, g_h);
    cudaGetSymbolAddress((void**)&qkv, g_qkv);
    cudaGetSymbolAddress((void**)&ctx, g_ctx);
    cudaGetSymbolAddress((void**)&h1, g_h1);
    cudaGetSymbolAddress((void**)&h2, g_h2);
    cudaGetSymbolAddress((void**)&ff, g_ff);
    cudaGetSymbolAddress((void**)&wqkv, g_wqkv);
    cudaGetSymbolAddress((void**)&wpr, g_wpr);
    cudaGetSymbolAddress((void**)&wfc, g_wfc);
    cudaGetSymbolAddress((void**)&wp2, g_wp2);

    // 0. fused prep: LN1 + all weight transposes
    prep_kernel<<<M_ + 6144, 256>>>(x, ln1_g, ln1_b, h,
                                    c_attn_w, wqkv, c_proj_w, wpr,
                                    fc_w, wfc, proj_w, wp2);
    // 2. qkv = h @ Wqkv + b  -> fp16
    tc_gemm<0><<<dim3(3 * D_ / 128, M_ / 256), 512, SMEM_GEMM>>>(
        h, wqkv, c_attn_b, nullptr, nullptr, qkv, 3 * D_, D_);
    // 3. attention -> ctx fp16
    attn_kernel<<<dim3(S_ / 128, H_, B_), 256, SMEM_ATTN>>>(qkv, ctx);
    // 4. h1 = x + ctx @ Wproj + b  (fp32 out)
    tc_gemm<2><<<dim3(D_ / 128, M_ / 256), 512, SMEM_GEMM>>>(
        ctx, wpr, c_proj_b, x, h1, nullptr, D_, D_);
    // 5. h2 = LN2(h1)  -> fp16
    ln_kernel<<<M_, 256>>>(h1, ln2_g, ln2_b, h2);
    // 6. ff = gelu(h2 @ fc_w + fc_b)  -> fp16
    tc_gemm<1><<<dim3(4 * D_ / 128, M_ / 256), 512, SMEM_GEMM>>>(
        h2, wfc, fc_b, nullptr, nullptr, ff, 4 * D_, D_);
    // 7. out = h1 + ff @ proj_w + proj_b  (fp32 out)
    tc_gemm<2><<<dim3(D_ / 128, M_ / 256), 512, SMEM_GEMM>>>(
        ff, wp2, proj_b, h1, out, nullptr, D_, 4 * D_);
}